// round 16
// baseline (speedup 1.0000x reference)
#include <cuda_runtime.h>
#include <math.h>
#include <stdint.h>

#define LDIM 512
#define BDIM 64
#define CDIM 512
#define RANKS 8
#define COLS 64           // alpha/E columns per rank
#define NGRP 4            // interleaved groups per cluster
#define GRPB 4            // batches per group
#define NCL  4            // clusters (4 x 16 batches = 64)

__device__ float g_logz[BDIM];
__device__ float g_scorep[BDIM];

// ---------------------------------------------------------------------------
__device__ __forceinline__ unsigned smem_u32(const void* p) {
    return (unsigned)__cvta_generic_to_shared(p);
}
__device__ __forceinline__ unsigned mapa_rank(unsigned saddr, unsigned rank) {
    unsigned r;
    asm("mapa.shared::cluster.u32 %0, %1, %2;" : "=r"(r) : "r"(saddr), "r"(rank));
    return r;
}
__device__ __forceinline__ void stc_f32(unsigned saddr, float v) {
    asm volatile("st.shared::cluster.f32 [%0], %1;" :: "r"(saddr), "f"(v) : "memory");
}
__device__ __forceinline__ void stc_v4(unsigned saddr, float4 v) {
    asm volatile("st.shared::cluster.v4.f32 [%0], {%1,%2,%3,%4};"
                 :: "r"(saddr), "f"(v.x), "f"(v.y), "f"(v.z), "f"(v.w) : "memory");
}
__device__ __forceinline__ void cluster_sync_() {
    asm volatile("barrier.cluster.arrive.aligned;" ::: "memory");
    asm volatile("barrier.cluster.wait.aligned;"   ::: "memory");
}
__device__ __forceinline__ unsigned long long ffma2(unsigned long long a,
                                                    unsigned long long b,
                                                    unsigned long long c) {
    unsigned long long d;
    asm("fma.rn.f32x2 %0, %1, %2, %3;" : "=l"(d) : "l"(a), "l"(b), "l"(c));
    return d;
}
__device__ __forceinline__ unsigned long long dup2(float v) {
    unsigned long long r; unsigned u = __float_as_uint(v);
    asm("mov.b64 %0, {%1, %1};" : "=l"(r) : "r"(u));
    return r;
}
__device__ __forceinline__ float2 unpk(unsigned long long v) {
    unsigned a, b;
    asm("mov.b64 {%0, %1}, %2;" : "=r"(a), "=r"(b) : "l"(v));
    return make_float2(__uint_as_float(a), __uint_as_float(b));
}
__device__ __forceinline__ void mbar_init(unsigned addr, unsigned cnt) {
    asm volatile("mbarrier.init.shared.b64 [%0], %1;" :: "r"(addr), "r"(cnt) : "memory");
}
__device__ __forceinline__ void mbar_arrive_remote(unsigned addr) {
    asm volatile("mbarrier.arrive.release.cluster.shared::cluster.b64 _, [%0];"
                 :: "r"(addr) : "memory");
}
__device__ __forceinline__ void mbar_wait_acq(unsigned addr, unsigned parity) {
    unsigned done;
    asm volatile(
        "{\n\t.reg .pred p;\n\t"
        "mbarrier.try_wait.parity.acquire.cluster.shared::cta.b64 p, [%1], %2;\n\t"
        "selp.b32 %0, 1, 0, p;\n\t}"
        : "=r"(done) : "r"(addr), "r"(parity) : "memory");
    if (!done) {
        asm volatile(
            "{\n\t.reg .pred P1;\n\t"
            "WL_%=:\n\t"
            "mbarrier.try_wait.parity.acquire.cluster.shared::cta.b64 P1, [%0], %1, 0x989680;\n\t"
            "@P1 bra.uni WD_%=;\n\t"
            "bra.uni WL_%=;\n\t"
            "WD_%=:\n\t}"
            :: "r"(addr), "r"(parity) : "memory");
    }
}
__device__ __forceinline__ int mask_byte_probe(const unsigned char* m8) {
    int allnz = 1;
    for (int b = 0; b < BDIM; b++) if (m8[b] == 0) allnz = 0;
    return allnz;
}
__device__ __forceinline__ int get_mask2(const void* mask, int idx, int isbyte) {
    if (isbyte) return ((const unsigned char*)mask)[idx] != 0;
    return ((const int*)mask)[idx] != 0;
}

// ---------------------------------------------------------------------------
struct __align__(16) SM {
    float E[CDIM * COLS];               // 128 KB  exp(trans) col-slice
    float pbuf[NGRP][2][CDIM][GRPB];    // 64 KB   assembled p per group/parity
    float part[16][GRPB][COLS];         // 16 KB   matvec partials (shared)
    float stage[COLS][GRPB];            // 1 KB    (single-buffer, barrier-fenced)
    float pmail[NGRP][2][RANKS][GRPB];  // 1 KB    lagged local maxes
    float wred[8];                      // current group's warp maxes
    float wredp[NGRP][8];               // prologue/final per-group
    float wsum[NGRP][8];
    float fm[RANKS][16], fs[RANKS][16];
    unsigned actw[LDIM];                // bit (g*4+gb)
    unsigned char anyg[NGRP][LDIM];
    unsigned long long mbar[NGRP][2];   // arrive count 8
    int isbyte;
};

__global__ void __cluster_dims__(RANKS, 1, 1) __launch_bounds__(512, 1)
forward_kernel(const float* __restrict__ emit,
               const void*  __restrict__ mask,
               const float* __restrict__ trans,
               const float* __restrict__ tfs,
               const float* __restrict__ tte)
{
    extern __shared__ char smraw[];
    SM* sm = (SM*)smraw;

    const int t     = threadIdx.x;
    const int cta   = blockIdx.x;
    const int rank  = cta & (RANKS - 1);
    const int cl    = cta >> 3;
    const int bbase = cl * 16;

    // owner mapping (t<256): gb = batch-in-group, col = local column
    const int gb   = (t >> 6) & 3;
    const int col  = t & 63;
    const int cg_glob = rank * COLS + col;
    const int lane = t & 31;
    const int wrp  = t >> 5;

    // matvec mapping: cg = 4-col group (16), bp = batch pair (2), seg = 32-row seg (16)
    const int cg  = t & 15;
    const int bp  = (t >> 4) & 1;
    const int seg = t >> 5;

    if (t == 0) {
        sm->isbyte = mask_byte_probe((const unsigned char*)mask);
        #pragma unroll
        for (int g = 0; g < NGRP; g++) {
            mbar_init(smem_u32(&sm->mbar[g][0]), RANKS);
            mbar_init(smem_u32(&sm->mbar[g][1]), RANKS);
        }
    }

    // ---- E slice = exp(trans[:, rank*64 .. +64]) ----
    for (int idx = t; idx < CDIM * COLS; idx += 512) {
        int row = idx >> 6, c = idx & 63;
        sm->E[idx] = expf(trans[(size_t)row * CDIM + rank * COLS + c]);
    }
    __syncthreads();

    // ---- mask flags (one i per thread) ----
    const int isbyte = sm->isbyte;
    {
        int i = t;
        unsigned w = 0;
        #pragma unroll
        for (int k = 0; k < 16; k++)
            w |= (unsigned)get_mask2(mask, i * BDIM + bbase + k, isbyte) << k;
        sm->actw[i] = w;
        #pragma unroll
        for (int g = 0; g < NGRP; g++)
            sm->anyg[g][i] = (unsigned char)((w >> (g * 4)) & 0xF ? 1 : 0);
    }

    // ---- alpha_0 for all 4 groups + per-group warp maxes ----
    float a[NGRP], m_used[NGRP];
    #pragma unroll
    for (int g = 0; g < NGRP; g++) { a[g] = 0.f; m_used[g] = 0.f; }
    if (t < 256) {
        #pragma unroll
        for (int g = 0; g < NGRP; g++) {
            a[g] = emit[(size_t)(bbase + g * 4 + gb) * CDIM + cg_glob] + tfs[cg_glob];
            float m = a[g];
            #pragma unroll
            for (int o = 16; o; o >>= 1) m = fmaxf(m, __shfl_xor_sync(0xffffffffu, m, o));
            if (lane == 0) sm->wredp[g][wrp] = m;
        }
    }
    __syncthreads();

    // ---- prologue: exchange alpha_0 local maxes for all 16 batches ----
    if (t < 128) {
        int dr = t >> 4, q = t & 15;                 // dest rank, batch idx
        float ml = fmaxf(sm->wredp[q >> 2][2 * (q & 3)], sm->wredp[q >> 2][2 * (q & 3) + 1]);
        stc_f32(mapa_rank(smem_u32(&sm->fm[0][0]), dr) + (unsigned)((rank * 16 + q) * 4), ml);
    }
    cluster_sync_();   // also publishes mbarrier inits cluster-wide

    // initial mail (rank-local maxes of alpha_0) is already known to all: fm
    if (t < 128) {                                    // g = t>>5, r = (t>>2)&7, gb2 = t&3
        int g = t >> 5, r = (t >> 2) & 7, gb2 = t & 3;
        sm->pmail[g][0][r][gb2] = sm->fm[r][g * 4 + gb2];
    }

    // per-warp push targets (warp w ships to rank w)
    const unsigned p_dst = (wrp < 8) ? mapa_rank(smem_u32(&sm->pbuf[0][0][0][0]), wrp) : 0u;
    const unsigned m_dst = (wrp < 8) ? mapa_rank(smem_u32(&sm->pmail[0][0][0][0]), wrp) : 0u;
    const unsigned b_dst = (wrp < 8) ? mapa_rank(smem_u32(&sm->mbar[0][0]), wrp) : 0u;

    // ---- initial p push for each group (parity 0) ----
    #pragma unroll
    for (int g = 0; g < NGRP; g++) {
        __syncthreads();
        if (t < 256) {
            float mg = sm->fm[0][g * 4 + gb];
            #pragma unroll
            for (int r = 1; r < RANKS; r++) mg = fmaxf(mg, sm->fm[r][g * 4 + gb]);
            m_used[g] = mg;
            sm->stage[col][gb] = __expf(a[g] - mg);
        }
        __syncthreads();
        if (wrp < 8) {
            const float4* s4 = (const float4*)&sm->stage[0][0];
            float4 v0 = s4[lane * 2], v1 = s4[lane * 2 + 1];
            unsigned off = (unsigned)(((g * 2 + 0) * CDIM + rank * COLS) * 16 + lane * 32);
            stc_v4(p_dst + off,      v0);
            stc_v4(p_dst + off + 16, v1);
            __syncwarp();
            if (lane == 0) mbar_arrive_remote(b_dst + (unsigned)((g * 2 + 0) * 8));
        }
    }

    const unsigned bar_l = smem_u32(&sm->mbar[0][0]);
    int uses[NGRP] = {0, 0, 0, 0};

    for (int i = 1; i < LDIM; i++) {
        // emit prefetch for all active groups
        float er[NGRP];
        const unsigned aw = sm->actw[i];
        if (t < 256) {
            #pragma unroll
            for (int g = 0; g < NGRP; g++)
                if (sm->anyg[g][i])
                    er[g] = emit[((size_t)i * BDIM + bbase + g * 4 + gb) * CDIM + cg_glob];
        }

        #pragma unroll
        for (int g = 0; g < NGRP; g++) {
            if (!sm->anyg[g][i]) continue;
            const int par = uses[g] & 1, ph = (uses[g] >> 1) & 1, np = par ^ 1;

            // ---- wait for all 8 ranks' p slices for this group's step ----
            mbar_wait_acq(bar_l + (unsigned)((g * 2 + par) * 8), (unsigned)ph);

            // ---- matvec: E (SMEM) x p[g][par], 2 batches x 4 cols x 32 rows ----
            {
                const ulonglong2* Ev = (const ulonglong2*)sm->E + seg * 32 * 16 + cg;
                const float2*     pv = (const float2*)&sm->pbuf[g][par][seg * 32][bp * 2];
                unsigned long long ac00 = 0, ac01 = 0, ac10 = 0, ac11 = 0;
                #pragma unroll
                for (int c = 0; c < 32; c++) {
                    ulonglong2 e  = Ev[c * 16];
                    float2     pq = pv[c * 2];
                    unsigned long long d0 = dup2(pq.x), d1 = dup2(pq.y);
                    ac00 = ffma2(d0, e.x, ac00); ac01 = ffma2(d0, e.y, ac01);
                    ac10 = ffma2(d1, e.x, ac10); ac11 = ffma2(d1, e.y, ac11);
                }
                float2 lo = unpk(ac00), hi = unpk(ac01);
                *(float4*)&sm->part[seg][bp * 2][cg * 4] = make_float4(lo.x, lo.y, hi.x, hi.y);
                lo = unpk(ac10); hi = unpk(ac11);
                *(float4*)&sm->part[seg][bp * 2 + 1][cg * 4] = make_float4(lo.x, lo.y, hi.x, hi.y);
            }
            __syncthreads();

            // ---- combine: update alpha, stage next p, warp maxes ----
            if (t < 256) {
                float s = 0.f;
                #pragma unroll
                for (int sg = 0; sg < 16; sg += 4)
                    s += (sm->part[sg][gb][col]     + sm->part[sg + 1][gb][col])
                       + (sm->part[sg + 2][gb][col] + sm->part[sg + 3][gb][col]);
                float m_next = sm->pmail[g][par][0][gb];
                #pragma unroll
                for (int r = 1; r < RANKS; r++)
                    m_next = fmaxf(m_next, sm->pmail[g][par][r][gb]);
                float anew = m_used[g] + __logf(s) + er[g];
                if ((aw >> (g * 4 + gb)) & 1) a[g] = anew;
                m_used[g] = m_next;
                sm->stage[col][gb] = __expf(a[g] - m_next);
                float m = a[g];
                #pragma unroll
                for (int o = 16; o; o >>= 1) m = fmaxf(m, __shfl_xor_sync(0xffffffffu, m, o));
                if (lane == 0) sm->wred[wrp] = m;
            }
            __syncthreads();

            // ---- push: warp w ships stage + mail to rank w, arrive [g][np] ----
            if (wrp < 8) {
                const float4* s4 = (const float4*)&sm->stage[0][0];
                float4 v0 = s4[lane * 2], v1 = s4[lane * 2 + 1];
                unsigned off = (unsigned)(((g * 2 + np) * CDIM + rank * COLS) * 16 + lane * 32);
                stc_v4(p_dst + off,      v0);
                stc_v4(p_dst + off + 16, v1);
                if (lane == 0) {
                    float4 mv = make_float4(fmaxf(sm->wred[0], sm->wred[1]),
                                            fmaxf(sm->wred[2], sm->wred[3]),
                                            fmaxf(sm->wred[4], sm->wred[5]),
                                            fmaxf(sm->wred[6], sm->wred[7]));
                    stc_v4(m_dst + (unsigned)(((g * 2 + np) * 8 + rank) * 16), mv);
                }
                __syncwarp();
                if (lane == 0) mbar_arrive_remote(b_dst + (unsigned)((g * 2 + np) * 8));
            }
            uses[g]++;
        }
    }

    __syncthreads();

    // ---- final: log_z for 16 batches across 8 ranks ----
    if (t < 256) {
        #pragma unroll
        for (int g = 0; g < NGRP; g++) {
            float v = a[g] + tte[cg_glob];
            float m = v;
            #pragma unroll
            for (int o = 16; o; o >>= 1) m = fmaxf(m, __shfl_xor_sync(0xffffffffu, m, o));
            if (lane == 0) sm->wredp[g][wrp] = m;
            // stash v via stage trick not needed: recompute below with smem maxes
        }
    }
    __syncthreads();
    if (t < 256) {
        #pragma unroll
        for (int g = 0; g < NGRP; g++) {
            float v = a[g] + tte[cg_glob];
            float mloc = fmaxf(sm->wredp[g][2 * gb], sm->wredp[g][2 * gb + 1]);
            float e = expf(v - mloc);
            #pragma unroll
            for (int o = 16; o; o >>= 1) e += __shfl_xor_sync(0xffffffffu, e, o);
            if (lane == 0) sm->wsum[g][wrp] = e;
        }
    }
    __syncthreads();
    if (t < 128) {
        int dr = t >> 4, q = t & 15;
        float ml = fmaxf(sm->wredp[q >> 2][2 * (q & 3)], sm->wredp[q >> 2][2 * (q & 3) + 1]);
        float sl = sm->wsum[q >> 2][2 * (q & 3)] + sm->wsum[q >> 2][2 * (q & 3) + 1];
        unsigned fmr = mapa_rank(smem_u32(&sm->fm[0][0]), dr);
        unsigned fsr = mapa_rank(smem_u32(&sm->fs[0][0]), dr);
        stc_f32(fmr + (unsigned)((rank * 16 + q) * 4), ml);
        stc_f32(fsr + (unsigned)((rank * 16 + q) * 4), sl);
    }
    cluster_sync_();
    if (rank == 0 && t < 16) {
        float mg = sm->fm[0][t];
        #pragma unroll
        for (int r = 1; r < RANKS; r++) mg = fmaxf(mg, sm->fm[r][t]);
        float tot = 0.f;
        #pragma unroll
        for (int r = 0; r < RANKS; r++) tot += sm->fs[r][t] * expf(sm->fm[r][t] - mg);
        g_logz[bbase + t] = mg + logf(tot);
    }
}

// ---------------------------------------------------------------------------
__global__ __launch_bounds__(512) void score_kernel(
    const float* __restrict__ emit,
    const int*   __restrict__ target,
    const void*  __restrict__ mask,
    const float* __restrict__ trans,
    const float* __restrict__ tfs,
    const float* __restrict__ tte)
{
    __shared__ int s_isbyte;
    __shared__ float red[16];
    const int t = threadIdx.x, warp = t >> 5, lane = t & 31;
    if (t == 0) s_isbyte = mask_byte_probe((const unsigned char*)mask);
    __syncthreads();
    const int isbyte = s_isbyte;

    const int idx = blockIdx.x * 512 + t;
    const int i = idx >> 6;
    const int b = idx & 63;

    float contrib = 0.f;
    if (get_mask2(mask, i * BDIM + b, isbyte)) {
        int ti = target[i * BDIM + b];
        contrib = emit[((size_t)i * BDIM + b) * CDIM + ti];
        if (i > 0) {
            int tp = target[(i - 1) * BDIM + b];
            contrib += trans[(size_t)tp * CDIM + ti];
        } else {
            contrib += tfs[ti];
        }
        int nxt = (i + 1 < LDIM) ? get_mask2(mask, (i + 1) * BDIM + b, isbyte) : 0;
        if (!nxt) contrib += tte[ti];
    }
    #pragma unroll
    for (int o = 16; o; o >>= 1) contrib += __shfl_xor_sync(0xffffffffu, contrib, o);
    if (lane == 0) red[warp] = contrib;
    __syncthreads();
    if (t == 0) {
        float s = 0.f;
        #pragma unroll
        for (int w = 0; w < 16; w++) s += red[w];
        g_scorep[blockIdx.x] = s;
    }
}

// ---------------------------------------------------------------------------
__global__ void finalize_kernel(float* __restrict__ out) {
    __shared__ float red[2];
    const int t = threadIdx.x, lane = t & 31, warp = t >> 5;
    float v = (t < BDIM) ? (g_logz[t] - g_scorep[t]) : 0.f;
    #pragma unroll
    for (int o = 16; o; o >>= 1) v += __shfl_xor_sync(0xffffffffu, v, o);
    if (lane == 0) red[warp] = v;
    __syncthreads();
    if (t == 0) out[0] = (red[0] + red[1]) / (float)BDIM;
}

// ---------------------------------------------------------------------------
extern "C" void kernel_launch(void* const* d_in, const int* in_sizes, int n_in,
                              void* d_out, int out_size) {
    const float* emit   = (const float*)d_in[0];
    const int*   target = (const int*)  d_in[1];
    const void*  mask   =               d_in[2];
    const float* trans  = (const float*)d_in[3];
    const float* tfs    = (const float*)d_in[4];
    const float* tte    = (const float*)d_in[5];
    float* out = (float*)d_out;

    cudaFuncSetAttribute(forward_kernel,
                         cudaFuncAttributeMaxDynamicSharedMemorySize, (int)sizeof(SM));

    forward_kernel<<<NCL * RANKS, 512, sizeof(SM)>>>(emit, mask, trans, tfs, tte);
    score_kernel<<<64, 512>>>(emit, target, mask, trans, tfs, tte);
    finalize_kernel<<<1, 64>>>(out);
}

// round 17
// speedup vs baseline: 1.8701x; 1.8701x over previous
#include <cuda_runtime.h>
#include <math.h>
#include <stdint.h>

#define LDIM 512
#define BDIM 64
#define CDIM 512

__device__ float g_logz[BDIM];
__device__ float g_scorep[BDIM];

// ---------------------------------------------------------------------------
__device__ __forceinline__ unsigned smem_u32(const void* p) {
    return (unsigned)__cvta_generic_to_shared(p);
}
__device__ __forceinline__ unsigned mapa_rank(unsigned saddr, unsigned rank) {
    unsigned r;
    asm("mapa.shared::cluster.u32 %0, %1, %2;" : "=r"(r) : "r"(saddr), "r"(rank));
    return r;
}
__device__ __forceinline__ void stc_f32(unsigned saddr, float v) {
    asm volatile("st.shared::cluster.f32 [%0], %1;" :: "r"(saddr), "f"(v) : "memory");
}
__device__ __forceinline__ void stc_v4(unsigned saddr, float4 v) {
    asm volatile("st.shared::cluster.v4.f32 [%0], {%1,%2,%3,%4};"
                 :: "r"(saddr), "f"(v.x), "f"(v.y), "f"(v.z), "f"(v.w) : "memory");
}
__device__ __forceinline__ void cluster_sync_() {
    asm volatile("barrier.cluster.arrive.aligned;" ::: "memory");
    asm volatile("barrier.cluster.wait.aligned;"   ::: "memory");
}
__device__ __forceinline__ unsigned long long ffma2(unsigned long long a,
                                                    unsigned long long b,
                                                    unsigned long long c) {
    unsigned long long d;
    asm("fma.rn.f32x2 %0, %1, %2, %3;" : "=l"(d) : "l"(a), "l"(b), "l"(c));
    return d;
}
__device__ __forceinline__ unsigned long long dup2(float v) {
    unsigned long long r; unsigned u = __float_as_uint(v);
    asm("mov.b64 %0, {%1, %1};" : "=l"(r) : "r"(u));
    return r;
}
__device__ __forceinline__ float2 unpk(unsigned long long v) {
    unsigned a, b;
    asm("mov.b64 {%0, %1}, %2;" : "=r"(a), "=r"(b) : "l"(v));
    return make_float2(__uint_as_float(a), __uint_as_float(b));
}
__device__ __forceinline__ void mbar_init(unsigned addr, unsigned cnt) {
    asm volatile("mbarrier.init.shared.b64 [%0], %1;" :: "r"(addr), "r"(cnt) : "memory");
}
__device__ __forceinline__ void mbar_arrive_remote(unsigned addr) {
    asm volatile("mbarrier.arrive.release.cluster.shared::cluster.b64 _, [%0];"
                 :: "r"(addr) : "memory");
}
__device__ __forceinline__ void mbar_wait_acq(unsigned addr, unsigned parity) {
    unsigned done;
    asm volatile(
        "{\n\t.reg .pred p;\n\t"
        "mbarrier.try_wait.parity.acquire.cluster.shared::cta.b64 p, [%1], %2;\n\t"
        "selp.b32 %0, 1, 0, p;\n\t}"
        : "=r"(done) : "r"(addr), "r"(parity) : "memory");
    if (!done) {
        asm volatile(
            "{\n\t.reg .pred P1;\n\t"
            "WL_%=:\n\t"
            "mbarrier.try_wait.parity.acquire.cluster.shared::cta.b64 P1, [%0], %1, 0x989680;\n\t"
            "@P1 bra.uni WD_%=;\n\t"
            "bra.uni WL_%=;\n\t"
            "WD_%=:\n\t}"
            :: "r"(addr), "r"(parity) : "memory");
    }
}
__device__ __forceinline__ int mask_byte_probe(const unsigned char* m8) {
    int allnz = 1;
    for (int b = 0; b < BDIM; b++) if (m8[b] == 0) allnz = 0;
    return allnz;
}
__device__ __forceinline__ int get_mask2(const void* mask, int idx, int isbyte) {
    if (isbyte) return ((const unsigned char*)mask)[idx] != 0;
    return ((const int*)mask)[idx] != 0;
}

// ============================================================================
// PRIMARY: 16-CTA clusters, 256 threads, 32 cols/rank, 2 CTAs per SM
// ============================================================================
#define R16 16
#define C16 32

struct __align__(16) SM16 {
    float E[CDIM * C16];            // 64 KB  exp(trans) 32-col slice
    float pbuf[2][CDIM][4];         // 16 KB  assembled p, double-buffered
    float part[16][4][C16];         // 8 KB   matvec partials
    float stage[C16][4];            // 512 B
    float pmail[2][R16][4];         // 512 B  lagged local maxes
    float wred[4];                  // batch-local maxes (warp g = batch g)
    float wsum[4];
    float fm[R16][4], fs[R16][4];
    unsigned char act4[LDIM][4];
    unsigned char any[LDIM];
    unsigned long long mbar[2];     // arrive count 16 per parity
    int isbyte;
};

__global__ void __cluster_dims__(R16, 1, 1) __launch_bounds__(256, 2)
forward16(const float* __restrict__ emit,
          const void*  __restrict__ mask,
          const float* __restrict__ trans,
          const float* __restrict__ tfs,
          const float* __restrict__ tte)
{
    extern __shared__ char smraw[];
    SM16* sm = (SM16*)smraw;

    const int t     = threadIdx.x;
    const int cta   = blockIdx.x;
    const int rank  = cta & (R16 - 1);
    const int cl    = cta >> 4;
    const int bbase = cl * 4;

    const int lane = t & 31;
    const int wrp  = t >> 5;              // 0..7

    // owner mapping (t<128): warp g owns batch g, lane = column
    const int g   = wrp;                   // valid for t<128 (g<4)
    const int col = lane;
    const int cg_glob = rank * C16 + col;

    // matvec mapping: cg4 = 4-col group (8), bp = batch pair (2), seg (16)
    const int cg4 = t & 7;
    const int bp  = (t >> 3) & 1;
    const int seg = t >> 4;

    if (t == 0) {
        sm->isbyte = mask_byte_probe((const unsigned char*)mask);
        mbar_init(smem_u32(&sm->mbar[0]), R16);
        mbar_init(smem_u32(&sm->mbar[1]), R16);
    }

    // ---- E slice = exp(trans[:, rank*32 .. +32]) ----
    for (int idx = t; idx < CDIM * C16; idx += 256) {
        int row = idx >> 5, c = idx & 31;
        sm->E[idx] = expf(trans[(size_t)row * CDIM + rank * C16 + c]);
    }
    __syncthreads();

    // ---- mask flags (2 i's per thread) ----
    const int isbyte = sm->isbyte;
    #pragma unroll
    for (int k = 0; k < 2; k++) {
        int i = t + k * 256;
        int anyv = 0;
        #pragma unroll
        for (int gg = 0; gg < 4; gg++) {
            int m = get_mask2(mask, i * BDIM + bbase + gg, isbyte);
            sm->act4[i][gg] = (unsigned char)m;
            anyv |= m;
        }
        sm->any[i] = (unsigned char)anyv;
    }

    // ---- alpha_0 + batch-local maxes (warp g = batch g) ----
    float a = 0.f, m_used = 0.f;
    if (t < 128) {
        a = emit[(size_t)(bbase + g) * CDIM + cg_glob] + tfs[cg_glob];
        float m = a;
        #pragma unroll
        for (int o = 16; o; o >>= 1) m = fmaxf(m, __shfl_xor_sync(0xffffffffu, m, o));
        if (lane == 0) sm->wred[g] = m;
    }
    __syncthreads();

    // ---- prologue: exact global max of alpha_0 across 16 ranks ----
    if (t < 64) {
        int dr = t >> 2, dg = t & 3;
        stc_f32(mapa_rank(smem_u32(&sm->fm[0][0]), dr) + (unsigned)((rank * 4 + dg) * 4),
                sm->wred[dg]);
    }
    cluster_sync_();   // also publishes mbarrier inits cluster-wide
    if (t < 128) {
        float mg = sm->fm[0][g];
        #pragma unroll
        for (int r = 1; r < R16; r++) mg = fmaxf(mg, sm->fm[r][g]);
        m_used = mg;
        sm->stage[col][g] = __expf(a - mg);
    }
    __syncthreads();

    // push targets: warp w ships to ranks 2w (lane path 0) and 2w+1 (path 1)
    const unsigned pb_base = smem_u32(&sm->pbuf[0][0][0]);
    const unsigned pm_base = smem_u32(&sm->pmail[0][0][0]);
    const unsigned mb_base = smem_u32(&sm->mbar[0]);
    const unsigned p_dst0 = mapa_rank(pb_base, 2 * wrp);
    const unsigned p_dst1 = mapa_rank(pb_base, 2 * wrp + 1);
    const unsigned m_dst  = (lane < 2) ? mapa_rank(pm_base, 2 * wrp + lane) : 0u;
    const unsigned b_dst  = (lane < 2) ? mapa_rank(mb_base, 2 * wrp + lane) : 0u;
    const unsigned bar_l  = mb_base;

    int uses = 0;
    for (int i = 1; i < LDIM; i++) {
        if (!sm->any[i]) continue;
        const int par = uses & 1, ph = (uses >> 1) & 1;

        // emit prefetch (consumed in combine)
        float e_reg = 0.f;
        if (t < 128) e_reg = emit[((size_t)i * BDIM + bbase + g) * CDIM + cg_glob];

        // ---- push: each warp ships the 512B stage + mail to its 2 ranks ----
        {
            float4 pv = ((const float4*)&sm->stage[0][0])[lane];
            unsigned off = (unsigned)((par * CDIM + rank * C16 + lane) * 16);
            stc_v4(p_dst0 + off, pv);
            stc_v4(p_dst1 + off, pv);
            if (lane < 2) {
                float4 mv = *(const float4*)&sm->wred[0];
                stc_v4(m_dst + (unsigned)((par * R16 + rank) * 16), mv);
            }
            __syncwarp();
            if (lane < 2) mbar_arrive_remote(b_dst + (unsigned)(par * 8));
        }

        // ---- wait for all 16 ranks' slices ----
        mbar_wait_acq(bar_l + (unsigned)(par * 8), (unsigned)ph);

        // ---- matvec: E (SMEM 64KB) x p, 32 rows x 4 cols x 2 batches/thread ----
        {
            const ulonglong2* Ev = (const ulonglong2*)sm->E + seg * 32 * 8 + cg4;
            const float2*     pv = (const float2*)&sm->pbuf[par][seg * 32][bp * 2];
            unsigned long long ac00 = 0, ac01 = 0, ac10 = 0, ac11 = 0;
            #pragma unroll
            for (int c = 0; c < 32; c++) {
                ulonglong2 e  = Ev[c * 8];
                float2     pq = pv[c * 2];
                unsigned long long d0 = dup2(pq.x), d1 = dup2(pq.y);
                ac00 = ffma2(d0, e.x, ac00); ac01 = ffma2(d0, e.y, ac01);
                ac10 = ffma2(d1, e.x, ac10); ac11 = ffma2(d1, e.y, ac11);
            }
            float2 lo = unpk(ac00), hi = unpk(ac01);
            *(float4*)&sm->part[seg][bp * 2][cg4 * 4] = make_float4(lo.x, lo.y, hi.x, hi.y);
            lo = unpk(ac10); hi = unpk(ac11);
            *(float4*)&sm->part[seg][bp * 2 + 1][cg4 * 4] = make_float4(lo.x, lo.y, hi.x, hi.y);
        }
        __syncthreads();

        // ---- combine: sum 16 segs, update alpha, stage next p, warp max ----
        if (t < 128) {
            float s = 0.f;
            #pragma unroll
            for (int sg = 0; sg < 16; sg += 4)
                s += (sm->part[sg][g][col]     + sm->part[sg + 1][g][col])
                   + (sm->part[sg + 2][g][col] + sm->part[sg + 3][g][col]);
            float m_next = sm->pmail[par][0][g];
            #pragma unroll
            for (int r = 1; r < R16; r++) m_next = fmaxf(m_next, sm->pmail[par][r][g]);
            float anew = m_used + __logf(s) + e_reg;
            if (sm->act4[i][g]) a = anew;
            m_used = m_next;
            sm->stage[col][g] = __expf(a - m_next);
            float m = a;
            #pragma unroll
            for (int o = 16; o; o >>= 1) m = fmaxf(m, __shfl_xor_sync(0xffffffffu, m, o));
            if (lane == 0) sm->wred[g] = m;
        }
        __syncthreads();
        uses++;
    }

    // ---- final: log_z = logsumexp(alpha + tte) across 16 ranks ----
    if (t < 128) {
        float v = a + tte[cg_glob];
        float m = v;
        #pragma unroll
        for (int o = 16; o; o >>= 1) m = fmaxf(m, __shfl_xor_sync(0xffffffffu, m, o));
        float e = expf(v - m);   // m = exact batch-local max (warp == batch)
        #pragma unroll
        for (int o = 16; o; o >>= 1) e += __shfl_xor_sync(0xffffffffu, e, o);
        if (lane == 0) { sm->wred[g] = m; sm->wsum[g] = e; }
    }
    __syncthreads();
    if (t < 4) {
        unsigned fm0 = mapa_rank(smem_u32(&sm->fm[0][0]), 0);
        unsigned fs0 = mapa_rank(smem_u32(&sm->fs[0][0]), 0);
        stc_f32(fm0 + (unsigned)((rank * 4 + t) * 4), sm->wred[t]);
        stc_f32(fs0 + (unsigned)((rank * 4 + t) * 4), sm->wsum[t]);
    }
    cluster_sync_();
    if (rank == 0 && t < 4) {
        float mg = sm->fm[0][t];
        #pragma unroll
        for (int r = 1; r < R16; r++) mg = fmaxf(mg, sm->fm[r][t]);
        float tot = 0.f;
        #pragma unroll
        for (int r = 0; r < R16; r++) tot += sm->fs[r][t] * expf(sm->fm[r][t] - mg);
        g_logz[bbase + t] = mg + logf(tot);
    }
}

// ============================================================================
// FALLBACK: proven R5 kernel (8-CTA clusters, 512 threads) — used only if
// 16-CTA clusters are unsupported at runtime.
// ============================================================================
#define R8 8
#define C8 64

struct __align__(16) SM8 {
    float E[CDIM * C8];
    float pbuf[2][CDIM][4];
    float part[32][4][C8];
    float stage[C8][4];
    float pmail[2][R8][4];
    float wred[8];
    float wsum[8];
    float fm[R8][4], fs[R8][4];
    unsigned char act4[LDIM][4];
    unsigned char any[LDIM];
    int isbyte;
};

__global__ void __cluster_dims__(R8, 1, 1) __launch_bounds__(512, 1)
forward8(const float* __restrict__ emit,
         const void*  __restrict__ mask,
         const float* __restrict__ trans,
         const float* __restrict__ tfs,
         const float* __restrict__ tte)
{
    extern __shared__ char smraw[];
    SM8* sm = (SM8*)smraw;

    const int t     = threadIdx.x;
    const int cta   = blockIdx.x;
    const int rank  = cta & (R8 - 1);
    const int cl    = cta >> 3;
    const int bbase = cl * 4;

    const int g    = (t >> 6) & 3;
    const int col  = t & 63;
    const int cg_glob = rank * C8 + col;
    const int lane = t & 31;
    const int wrp  = t >> 5;
    const int cg  = t & 15;
    const int seg = t >> 4;

    if (t == 0) sm->isbyte = mask_byte_probe((const unsigned char*)mask);

    for (int idx = t; idx < CDIM * C8; idx += 512) {
        int row = idx >> 6, c = idx & 63;
        sm->E[idx] = expf(trans[(size_t)row * CDIM + rank * C8 + c]);
    }
    __syncthreads();

    const int isbyte = sm->isbyte;
    {
        int i = t;
        int anyv = 0;
        #pragma unroll
        for (int gg = 0; gg < 4; gg++) {
            int m = get_mask2(mask, i * BDIM + bbase + gg, isbyte);
            sm->act4[i][gg] = (unsigned char)m;
            anyv |= m;
        }
        sm->any[i] = (unsigned char)anyv;
    }

    float a = 0.f, m_used = 0.f;
    if (t < 256) {
        a = emit[(size_t)(bbase + g) * CDIM + cg_glob] + tfs[cg_glob];
        float m = a;
        #pragma unroll
        for (int o = 16; o; o >>= 1) m = fmaxf(m, __shfl_xor_sync(0xffffffffu, m, o));
        if (lane == 0) sm->wred[wrp] = m;
    }
    __syncthreads();

    if (t < 32) {
        int dr = t >> 2, dg = t & 3;
        float ml = fmaxf(sm->wred[2 * dg], sm->wred[2 * dg + 1]);
        stc_f32(mapa_rank(smem_u32(&sm->fm[0][0]), dr) + (unsigned)((rank * 4 + dg) * 4), ml);
    }
    cluster_sync_();
    if (t < 256) {
        float mg = sm->fm[0][g];
        #pragma unroll
        for (int r = 1; r < R8; r++) mg = fmaxf(mg, sm->fm[r][g]);
        m_used = mg;
        sm->stage[col][g] = __expf(a - mg);
    }
    __syncthreads();

    unsigned p_dst = 0, m_dst = 0;
    if (wrp < 8) {
        p_dst = mapa_rank(smem_u32(&sm->pbuf[0][0][0]), wrp);
        m_dst = mapa_rank(smem_u32(&sm->pmail[0][0][0]), wrp);
    }

    int par = 0;
    for (int i = 1; i < LDIM; i++) {
        if (!sm->any[i]) continue;

        float e_reg = 0.f;
        if (t < 256) {
            e_reg = emit[((size_t)i * BDIM + bbase + g) * CDIM + cg_glob];
            const float4* st4 = (const float4*)&sm->stage[0][0];
            float4 v0 = st4[lane * 2], v1 = st4[lane * 2 + 1];
            unsigned off = (unsigned)((par * CDIM + rank * C8) * 16);
            stc_v4(p_dst + off + (unsigned)(lane * 32),      v0);
            stc_v4(p_dst + off + (unsigned)(lane * 32 + 16), v1);
            if (lane == 0) {
                float4 mv = make_float4(fmaxf(sm->wred[0], sm->wred[1]),
                                        fmaxf(sm->wred[2], sm->wred[3]),
                                        fmaxf(sm->wred[4], sm->wred[5]),
                                        fmaxf(sm->wred[6], sm->wred[7]));
                stc_v4(m_dst + (unsigned)((par * R8 + rank) * 16), mv);
            }
        }
        cluster_sync_();

        {
            const ulonglong2* Ev = (const ulonglong2*)sm->E + seg * 16 * (C8 / 4) + cg;
            const float4*     pv = (const float4*)&sm->pbuf[par][seg * 16][0];
            unsigned long long ac[8];
            #pragma unroll
            for (int k = 0; k < 8; k++) ac[k] = 0ull;
            #pragma unroll
            for (int c = 0; c < 16; c++) {
                ulonglong2 e  = Ev[c * (C8 / 4)];
                float4     pq = pv[c];
                unsigned long long d0 = dup2(pq.x), d1 = dup2(pq.y),
                                   d2 = dup2(pq.z), d3 = dup2(pq.w);
                ac[0] = ffma2(d0, e.x, ac[0]); ac[1] = ffma2(d0, e.y, ac[1]);
                ac[2] = ffma2(d1, e.x, ac[2]); ac[3] = ffma2(d1, e.y, ac[3]);
                ac[4] = ffma2(d2, e.x, ac[4]); ac[5] = ffma2(d2, e.y, ac[5]);
                ac[6] = ffma2(d3, e.x, ac[6]); ac[7] = ffma2(d3, e.y, ac[7]);
            }
            #pragma unroll
            for (int gg = 0; gg < 4; gg++) {
                float2 lo = unpk(ac[2 * gg]), hi = unpk(ac[2 * gg + 1]);
                *(float4*)&sm->part[seg][gg][cg * 4] = make_float4(lo.x, lo.y, hi.x, hi.y);
            }
        }
        __syncthreads();

        if (t < 256) {
            float s = 0.f;
            #pragma unroll
            for (int r = 0; r < R8; r++)
                s += (sm->part[4 * r][g][col]     + sm->part[4 * r + 1][g][col])
                   + (sm->part[4 * r + 2][g][col] + sm->part[4 * r + 3][g][col]);
            float m_next = sm->pmail[par][0][g];
            #pragma unroll
            for (int r = 1; r < R8; r++) m_next = fmaxf(m_next, sm->pmail[par][r][g]);
            float anew = m_used + __logf(s) + e_reg;
            if (sm->act4[i][g]) a = anew;
            m_used = m_next;
            sm->stage[col][g] = __expf(a - m_next);
            float m = a;
            #pragma unroll
            for (int o = 16; o; o >>= 1) m = fmaxf(m, __shfl_xor_sync(0xffffffffu, m, o));
            if (lane == 0) sm->wred[wrp] = m;
        }
        __syncthreads();
        par ^= 1;
    }

    float v = -3.4e38f;
    if (t < 256) v = a + tte[cg_glob];
    {
        float m = v;
        #pragma unroll
        for (int o = 16; o; o >>= 1) m = fmaxf(m, __shfl_xor_sync(0xffffffffu, m, o));
        if (t < 256 && lane == 0) sm->wred[wrp] = m;
    }
    __syncthreads();
    if (t < 256) {
        float mloc = fmaxf(sm->wred[2 * g], sm->wred[2 * g + 1]);
        float e = expf(v - mloc);
        #pragma unroll
        for (int o = 16; o; o >>= 1) e += __shfl_xor_sync(0xffffffffu, e, o);
        if (lane == 0) sm->wsum[wrp] = e;
    }
    __syncthreads();
    if (t < 4) {
        float ml = fmaxf(sm->wred[2 * t], sm->wred[2 * t + 1]);
        float sl = sm->wsum[2 * t] + sm->wsum[2 * t + 1];
        unsigned fm0 = mapa_rank(smem_u32(&sm->fm[0][0]), 0);
        unsigned fs0 = mapa_rank(smem_u32(&sm->fs[0][0]), 0);
        stc_f32(fm0 + (unsigned)((rank * 4 + t) * 4), ml);
        stc_f32(fs0 + (unsigned)((rank * 4 + t) * 4), sl);
    }
    cluster_sync_();
    if (rank == 0 && t < 4) {
        float mg = sm->fm[0][t];
        #pragma unroll
        for (int r = 1; r < R8; r++) mg = fmaxf(mg, sm->fm[r][t]);
        float tot = 0.f;
        #pragma unroll
        for (int r = 0; r < R8; r++) tot += sm->fs[r][t] * expf(sm->fm[r][t] - mg);
        g_logz[bbase + t] = mg + logf(tot);
    }
}

// ---------------------------------------------------------------------------
__global__ __launch_bounds__(512) void score_kernel(
    const float* __restrict__ emit,
    const int*   __restrict__ target,
    const void*  __restrict__ mask,
    const float* __restrict__ trans,
    const float* __restrict__ tfs,
    const float* __restrict__ tte)
{
    __shared__ int s_isbyte;
    __shared__ float red[16];
    const int t = threadIdx.x, warp = t >> 5, lane = t & 31;
    if (t == 0) s_isbyte = mask_byte_probe((const unsigned char*)mask);
    __syncthreads();
    const int isbyte = s_isbyte;

    const int idx = blockIdx.x * 512 + t;
    const int i = idx >> 6;
    const int b = idx & 63;

    float contrib = 0.f;
    if (get_mask2(mask, i * BDIM + b, isbyte)) {
        int ti = target[i * BDIM + b];
        contrib = emit[((size_t)i * BDIM + b) * CDIM + ti];
        if (i > 0) {
            int tp = target[(i - 1) * BDIM + b];
            contrib += trans[(size_t)tp * CDIM + ti];
        } else {
            contrib += tfs[ti];
        }
        int nxt = (i + 1 < LDIM) ? get_mask2(mask, (i + 1) * BDIM + b, isbyte) : 0;
        if (!nxt) contrib += tte[ti];
    }
    #pragma unroll
    for (int o = 16; o; o >>= 1) contrib += __shfl_xor_sync(0xffffffffu, contrib, o);
    if (lane == 0) red[warp] = contrib;
    __syncthreads();
    if (t == 0) {
        float s = 0.f;
        #pragma unroll
        for (int w = 0; w < 16; w++) s += red[w];
        g_scorep[blockIdx.x] = s;
    }
}

// ---------------------------------------------------------------------------
__global__ void finalize_kernel(float* __restrict__ out) {
    __shared__ float red[2];
    const int t = threadIdx.x, lane = t & 31, warp = t >> 5;
    float v = (t < BDIM) ? (g_logz[t] - g_scorep[t]) : 0.f;
    #pragma unroll
    for (int o = 16; o; o >>= 1) v += __shfl_xor_sync(0xffffffffu, v, o);
    if (lane == 0) red[warp] = v;
    __syncthreads();
    if (t == 0) out[0] = (red[0] + red[1]) / (float)BDIM;
}

// ---------------------------------------------------------------------------
extern "C" void kernel_launch(void* const* d_in, const int* in_sizes, int n_in,
                              void* d_out, int out_size) {
    const float* emit   = (const float*)d_in[0];
    const int*   target = (const int*)  d_in[1];
    const void*  mask   =               d_in[2];
    const float* trans  = (const float*)d_in[3];
    const float* tfs    = (const float*)d_in[4];
    const float* tte    = (const float*)d_in[5];
    float* out = (float*)d_out;

    cudaFuncSetAttribute(forward16,
                         cudaFuncAttributeMaxDynamicSharedMemorySize, (int)sizeof(SM16));
    cudaFuncSetAttribute(forward8,
                         cudaFuncAttributeMaxDynamicSharedMemorySize, (int)sizeof(SM8));

    // Runtime capability check for 16-CTA (nonportable) clusters — pure host
    // queries, deterministic, no allocation, capture-legal.
    int use16 = 0;
    if (cudaFuncSetAttribute(forward16,
                             cudaFuncAttributeNonPortableClusterSizeAllowed, 1)
        == cudaSuccess) {
        cudaLaunchConfig_t cfg = {};
        cfg.gridDim = dim3(16 * R16, 1, 1);
        cfg.blockDim = dim3(256, 1, 1);
        cfg.dynamicSmemBytes = sizeof(SM16);
        cudaLaunchAttribute attr[1];
        attr[0].id = cudaLaunchAttributeClusterDimension;
        attr[0].val.clusterDim.x = R16;
        attr[0].val.clusterDim.y = 1;
        attr[0].val.clusterDim.z = 1;
        cfg.attrs = attr;
        cfg.numAttrs = 1;
        int ncl = 0;
        if (cudaOccupancyMaxActiveClusters(&ncl, forward16, &cfg) == cudaSuccess
            && ncl > 0)
            use16 = 1;
    }
    cudaGetLastError();   // clear any sticky error from the probe

    if (use16)
        forward16<<<16 * R16, 256, sizeof(SM16)>>>(emit, mask, trans, tfs, tte);
    else
        forward8<<<16 * R8, 512, sizeof(SM8)>>>(emit, mask, trans, tfs, tte);

    score_kernel<<<64, 512>>>(emit, target, mask, trans, tfs, tte);
    finalize_kernel<<<1, 64>>>(out);
}